// round 6
// baseline (speedup 1.0000x reference)
#include <cuda_runtime.h>
#include <cuda_bf16.h>
#include <math.h>

// SSD detection post-processing, FUSED single kernel:
// scan slices -> last-arriving CTA per batch does sort+NMS+write.
//   d_in[0]: loc_data   [64, 72192, 4] float32
//   d_in[1]: conf_data  [64*72192, 2]  float32
//   d_in[2]: prior_data [72192, 4]     float32
// Output: [64, 2, 200, 5] float32 (class 0 zeros; class 1 = NMS results)

#define NUM_PRIORS 72192
#define BATCH      64
#define TOP_K      200
#define CAND_BUF   512
#define HIST_BINS  4096
#define BIN_SHIFT  14
#define BIN_OFF    61440
#define CONF_TH    0.01f
#define NMS_TH     0.45f
#define SPEC_TH    0.9958f      // expected ~303 survivors/batch (uniform scores)
#define NWORDS     7            // ceil(200/32)
#define SLICES     16
#define PRIORS_PER_SLICE (NUM_PRIORS / SLICES)   // 4512
#define NT         512

// ---- global scratch (zero-initialized at load; last CTA re-zeroes per batch) ----
__device__ unsigned long long g_cand[BATCH][CAND_BUF];
__device__ int g_cnt[BATCH];
__device__ int g_nconf[BATCH];
__device__ int g_done[BATCH];

struct Smem {
    unsigned long long cand[CAND_BUF];   // 4 KB
    int      hist[HIST_BINS];            // 16 KB (fallback only)
    float    bx0[TOP_K], by0[TOP_K], bx1[TOP_K], by1[TOP_K];
    float    score[TOP_K], area[TOP_K];
    unsigned sup[TOP_K][8];
    unsigned keepw[8];
    int      counter;
    int      thrbin;
    int      is_last;
};

__device__ __forceinline__ int score_bin(unsigned ub) {
    int v = (int)(ub >> BIN_SHIFT) - BIN_OFF;
    return v < 0 ? 0 : (v > HIST_BINS - 1 ? HIST_BINS - 1 : v);
}

__global__ __launch_bounds__(NT, 1)
void ssd_fused_kernel(const float4* __restrict__ conf4,
                      const float* __restrict__ loc,
                      const float2* __restrict__ conf2,
                      const float* __restrict__ prior,
                      float* __restrict__ out)
{
    extern __shared__ unsigned char smem_raw[];
    Smem& s = *reinterpret_cast<Smem*>(smem_raw);

    const int b     = blockIdx.y;
    const int slice = blockIdx.x;
    const int tid   = threadIdx.x;

    // ============================ phase 1: scan + gather ============================
    {
        const int pair_base = (b * NUM_PRIORS + slice * PRIORS_PER_SLICE) >> 1;
        const int npairs    = PRIORS_PER_SLICE >> 1;      // 2256
        const int p_base    = slice * PRIORS_PER_SLICE;

        int nconf = 0;
        for (int i = tid; i < npairs; i += NT) {
            float4 v = conf4[pair_base + i];
            int p0 = p_base + 2 * i;
            nconf += (v.y > CONF_TH) + (v.w > CONF_TH);
            if (v.y >= SPEC_TH) {
                int q = atomicAdd(&g_cnt[b], 1);
                if (q < CAND_BUF)
                    g_cand[b][q] = ((unsigned long long)__float_as_uint(v.y) << 32)
                                 | (unsigned)(~p0);
            }
            if (v.w >= SPEC_TH) {
                int q = atomicAdd(&g_cnt[b], 1);
                if (q < CAND_BUF)
                    g_cand[b][q] = ((unsigned long long)__float_as_uint(v.w) << 32)
                                 | (unsigned)(~(p0 + 1));
            }
        }
        #pragma unroll
        for (int o = 16; o > 0; o >>= 1) nconf += __shfl_down_sync(0xffffffffu, nconf, o);
        if ((tid & 31) == 0 && nconf) atomicAdd(&g_nconf[b], nconf);
    }

    // ---- arrival ticket: last CTA for this batch continues ----
    __threadfence();
    __syncthreads();
    if (tid == 0) {
        int prev = atomicAdd(&g_done[b], 1);
        s.is_last = (prev == SLICES - 1);
    }
    __syncthreads();
    if (!s.is_last) return;

    // ============================ phase 2: sort + NMS + write (last CTA) ============================
    const int cnt   = g_cnt[b];
    const int nconf = g_nconf[b];
    __syncthreads();
    if (tid == 0) { g_cnt[b] = 0; g_nconf[b] = 0; g_done[b] = 0; }  // reset for replay

    unsigned long long v;   // key owned by this thread (slot tid)

    if (cnt <= CAND_BUF && (cnt >= TOP_K || cnt == nconf)) {
        v = (tid < cnt) ? g_cand[b][tid] : 0ull;
    } else {
        // ---- exact fallback: full histogram select ----
        const float2* cb = conf2 + (size_t)b * NUM_PRIORS;
        for (int i = tid; i < HIST_BINS; i += NT) s.hist[i] = 0;
        if (tid == 0) { s.counter = 0; s.thrbin = 0; }
        __syncthreads();
        for (int p = tid; p < NUM_PRIORS; p += NT) {
            float sc = cb[p].y;
            if (sc > CONF_TH) atomicAdd(&s.hist[score_bin(__float_as_uint(sc))], 1);
        }
        __syncthreads();
        if (tid == 0) {
            int cum = 0, thr = 0;
            for (int vb = HIST_BINS - 1; vb >= 0; --vb) {
                cum += s.hist[vb];
                if (cum >= TOP_K) { thr = vb; break; }
            }
            s.thrbin = thr;
        }
        __syncthreads();
        const int thr = s.thrbin;
        s.cand[tid] = 0ull;
        __syncthreads();
        for (int p = tid; p < NUM_PRIORS; p += NT) {
            float sc = cb[p].y;
            unsigned ub = __float_as_uint(sc);
            if (sc > CONF_TH && score_bin(ub) >= thr) {
                int q = atomicAdd(&s.counter, 1);
                if (q < CAND_BUF)
                    s.cand[q] = ((unsigned long long)ub << 32) | (unsigned)(~p);
            }
        }
        __syncthreads();
        v = s.cand[tid];
    }

    // ---- hybrid bitonic sort, 512 keys descending ----
    #pragma unroll
    for (int k2 = 2; k2 <= CAND_BUF; k2 <<= 1) {
        #pragma unroll
        for (int j = k2 >> 1; j > 0; j >>= 1) {
            bool up    = (tid & k2) == 0;
            bool lower = (tid & j) == 0;
            bool keep_max = (up == lower);
            unsigned long long o;
            if (j >= 32) {
                s.cand[tid] = v;
                __syncthreads();
                o = s.cand[tid ^ j];
                __syncthreads();
            } else {
                o = __shfl_xor_sync(0xffffffffu, v, j);
            }
            v = keep_max ? (v >= o ? v : o) : (v >= o ? o : v);
        }
    }

    // ---- decode top-200 ----
    if (tid < TOP_K) {
        float sc  = __uint_as_float((unsigned)(v >> 32));
        int   idx = (int)(~(unsigned)v);
        bool valid = sc > CONF_TH;
        float x0 = 0.f, y0 = 0.f, x1 = 0.f, y1 = 0.f;
        if (valid) {
            const float4 l  = __ldg((const float4*)(loc + ((size_t)b * NUM_PRIORS + idx) * 4));
            const float4 pr = __ldg((const float4*)(prior + (size_t)idx * 4));
            float cx = pr.x + l.x * 0.1f * pr.z;
            float cy = pr.y + l.y * 0.1f * pr.w;
            float w  = pr.z * expf(l.z * 0.2f);
            float h  = pr.w * expf(l.w * 0.2f);
            x0 = cx - w * 0.5f; y0 = cy - h * 0.5f;
            x1 = cx + w * 0.5f; y1 = cy + h * 0.5f;
        }
        s.bx0[tid] = x0; s.by0[tid] = y0;
        s.bx1[tid] = x1; s.by1[tid] = y1;
        s.score[tid] = sc;
        s.area[tid]  = (x1 - x0) * (y1 - y0);
    }
    if (tid < 8) s.keepw[tid] = 0u;
    __syncthreads();

    // ---- build 200x200 suppression bitmask (ballots) ----
    {
        const int warp = tid >> 5, lane = tid & 31;
        for (int i = warp; i < TOP_K; i += NT / 32) {
            float ix0 = s.bx0[i], iy0 = s.by0[i];
            float ix1 = s.bx1[i], iy1 = s.by1[i];
            float ia  = s.area[i];
            #pragma unroll
            for (int w = 0; w < NWORDS; ++w) {
                int j = (w << 5) + lane;
                bool sup = false;
                if (j < TOP_K && j > i) {
                    float ww = fminf(ix1, s.bx1[j]) - fmaxf(ix0, s.bx0[j]);
                    float hh = fminf(iy1, s.by1[j]) - fmaxf(iy0, s.by0[j]);
                    ww = fmaxf(ww, 0.f); hh = fmaxf(hh, 0.f);
                    float inter = ww * hh;
                    float uni = ia + s.area[j] - inter;
                    sup = inter > NMS_TH * fmaxf(uni, 1e-12f);
                }
                unsigned bal = __ballot_sync(0xffffffffu, sup);
                if (lane == 0) s.sup[i][w] = bal;
            }
        }
        if (warp < NWORDS) {
            int j = (warp << 5) + lane;
            bool val = (j < TOP_K) && (s.score[j] > CONF_TH);
            unsigned bal = __ballot_sync(0xffffffffu, val);
            if (lane == 0) s.keepw[warp] = bal;
        }
    }
    __syncthreads();

    // ---- warp-serial NMS fold ----
    if (tid < 32) {
        unsigned mask = (tid < NWORDS) ? s.keepw[tid] : 0u;
        for (int i = 0; i < TOP_K; ++i) {
            unsigned wi = __shfl_sync(0xffffffffu, mask, i >> 5);
            if ((wi >> (i & 31)) & 1u) {
                if (tid < NWORDS) mask &= ~s.sup[i][tid];
            }
        }
        if (tid < NWORDS) s.keepw[tid] = mask;
    }
    __syncthreads();

    // ---- write output ----
    float* ob = out + (size_t)b * 2 * TOP_K * 5;
    for (int i = tid; i < 2 * TOP_K * 5; i += NT) ob[i] = 0.f;
    __syncthreads();

    if (tid < TOP_K) {
        int w = tid >> 5, bit = tid & 31;
        unsigned mw = s.keepw[w];
        if ((mw >> bit) & 1u) {
            int pos = 0;
            #pragma unroll
            for (int k = 0; k < NWORDS; ++k)
                if (k < w) pos += __popc(s.keepw[k]);
            pos += __popc(mw & ((1u << bit) - 1u));
            float* r = ob + (size_t)TOP_K * 5 + (size_t)pos * 5;
            r[0] = s.score[tid];
            r[1] = s.bx0[tid];
            r[2] = s.by0[tid];
            r[3] = s.bx1[tid];
            r[4] = s.by1[tid];
        }
    }
}

extern "C" void kernel_launch(void* const* d_in, const int* in_sizes, int n_in,
                              void* d_out, int out_size)
{
    const float*  locp  = (const float*)d_in[0];
    const float2* conf2 = (const float2*)d_in[1];
    const float4* conf4 = (const float4*)d_in[1];
    const float*  prior = (const float*)d_in[2];
    float* out = (float*)d_out;

    const int smem_bytes = (int)sizeof(Smem);
    cudaFuncSetAttribute(ssd_fused_kernel, cudaFuncAttributeMaxDynamicSharedMemorySize, smem_bytes);
    dim3 grid(SLICES, BATCH);
    ssd_fused_kernel<<<grid, NT, smem_bytes>>>(conf4, locp, conf2, prior, out);
}

// round 7
// speedup vs baseline: 1.5251x; 1.5251x over previous
#include <cuda_runtime.h>
#include <cuda_bf16.h>
#include <math.h>

// SSD detection post-processing, two-phase (fusion reverted: it serialized).
//   d_in[0]: loc_data   [64, 72192, 4] float32
//   d_in[1]: conf_data  [64*72192, 2]  float32
//   d_in[2]: prior_data [72192, 4]     float32
// Output: [64, 2, 200, 5] float32 (class 0 zeros; class 1 = NMS results)

#define NUM_PRIORS 72192
#define BATCH      64
#define TOP_K      200
#define CAND_BUF   512
#define HIST_BINS  4096
#define BIN_SHIFT  14
#define BIN_OFF    61440
#define CONF_TH    0.01f
#define NMS_TH     0.45f
#define SPEC_TH    0.9958f      // expected ~303 survivors/batch (uniform scores)
#define NWORDS     7            // ceil(200/32)
#define SLICES     32
#define PRIORS_PER_SLICE (NUM_PRIORS / SLICES)   // 2256
#define FINAL_NT   512

// ---- global scratch (zero-init at load; final_kernel self-resets) ----
__device__ unsigned long long g_cand[BATCH][CAND_BUF];
__device__ int g_cnt[BATCH];
__device__ int g_nconf[BATCH];

// ============================ kernel A: scan + gather ============================
__global__ __launch_bounds__(256)
void scan_kernel(const float4* __restrict__ conf4)
{
    const int b     = blockIdx.y;
    const int slice = blockIdx.x;
    const int tid   = threadIdx.x;

    const int pair_base = (b * NUM_PRIORS + slice * PRIORS_PER_SLICE) >> 1;
    const int npairs    = PRIORS_PER_SLICE >> 1;          // 1128
    const int p_base    = slice * PRIORS_PER_SLICE;

    int nconf = 0;
    for (int i = tid; i < npairs; i += 256) {
        float4 v = conf4[pair_base + i];
        int p0 = p_base + 2 * i;
        nconf += (v.y > CONF_TH) + (v.w > CONF_TH);
        if (v.y >= SPEC_TH) {
            int q = atomicAdd(&g_cnt[b], 1);
            if (q < CAND_BUF)
                g_cand[b][q] = ((unsigned long long)__float_as_uint(v.y) << 32)
                             | (unsigned)(~p0);
        }
        if (v.w >= SPEC_TH) {
            int q = atomicAdd(&g_cnt[b], 1);
            if (q < CAND_BUF)
                g_cand[b][q] = ((unsigned long long)__float_as_uint(v.w) << 32)
                             | (unsigned)(~(p0 + 1));
        }
    }
    #pragma unroll
    for (int o = 16; o > 0; o >>= 1) nconf += __shfl_down_sync(0xffffffffu, nconf, o);
    if ((tid & 31) == 0 && nconf) atomicAdd(&g_nconf[b], nconf);
}

// ============================ kernel B: sort + NMS + write ============================
struct Smem {
    unsigned long long cand[CAND_BUF];   // 4 KB
    int      hist[HIST_BINS];            // 16 KB (fallback only)
    float    bx0[TOP_K], by0[TOP_K], bx1[TOP_K], by1[TOP_K];
    float    score[TOP_K], area[TOP_K];
    unsigned sup[TOP_K][8];
    unsigned keepw[8];
    int      counter;
    int      thrbin;
};

__device__ __forceinline__ int score_bin(unsigned ub) {
    int v = (int)(ub >> BIN_SHIFT) - BIN_OFF;
    return v < 0 ? 0 : (v > HIST_BINS - 1 ? HIST_BINS - 1 : v);
}

// Register-resident word-serial NMS fold. k[] indices are compile-time
// (template W + unrolled w2) so the keep words stay in registers.
template<int W>
__device__ __forceinline__ void fold_word(unsigned (&k)[NWORDS],
                                          const unsigned (*sup)[8], int nbits)
{
    #pragma unroll 4
    for (int bit = 0; bit < nbits; ++bit) {
        if ((k[W] >> bit) & 1u) {
            const unsigned* r = sup[(W << 5) + bit];
            #pragma unroll
            for (int w2 = W; w2 < NWORDS; ++w2) k[w2] &= ~r[w2];
        }
    }
}

__global__ __launch_bounds__(FINAL_NT, 1)
void final_kernel(const float* __restrict__ loc,
                  const float2* __restrict__ conf2,
                  const float* __restrict__ prior,
                  float* __restrict__ out)
{
    extern __shared__ unsigned char smem_raw[];
    Smem& s = *reinterpret_cast<Smem*>(smem_raw);

    const int b   = blockIdx.x;
    const int tid = threadIdx.x;
    const int NT  = FINAL_NT;

    const int cnt   = g_cnt[b];
    const int nconf = g_nconf[b];
    __syncthreads();
    if (tid == 0) { g_cnt[b] = 0; g_nconf[b] = 0; }   // self-reset for replay

    unsigned long long v;

    if (cnt <= CAND_BUF && (cnt >= TOP_K || cnt == nconf)) {
        v = (tid < cnt) ? g_cand[b][tid] : 0ull;
    } else {
        // ---- exact fallback: full histogram select ----
        const float2* cb = conf2 + (size_t)b * NUM_PRIORS;
        for (int i = tid; i < HIST_BINS; i += NT) s.hist[i] = 0;
        if (tid == 0) { s.counter = 0; s.thrbin = 0; }
        __syncthreads();
        for (int p = tid; p < NUM_PRIORS; p += NT) {
            float sc = cb[p].y;
            if (sc > CONF_TH) atomicAdd(&s.hist[score_bin(__float_as_uint(sc))], 1);
        }
        __syncthreads();
        if (tid == 0) {
            int cum = 0, thr = 0;
            for (int vb = HIST_BINS - 1; vb >= 0; --vb) {
                cum += s.hist[vb];
                if (cum >= TOP_K) { thr = vb; break; }
            }
            s.thrbin = thr;
        }
        __syncthreads();
        const int thr = s.thrbin;
        s.cand[tid] = 0ull;
        __syncthreads();
        for (int p = tid; p < NUM_PRIORS; p += NT) {
            float sc = cb[p].y;
            unsigned ub = __float_as_uint(sc);
            if (sc > CONF_TH && score_bin(ub) >= thr) {
                int q = atomicAdd(&s.counter, 1);
                if (q < CAND_BUF)
                    s.cand[q] = ((unsigned long long)ub << 32) | (unsigned)(~p);
            }
        }
        __syncthreads();
        v = s.cand[tid];
    }

    // ---- hybrid bitonic sort, 512 keys descending ----
    #pragma unroll
    for (int k2 = 2; k2 <= CAND_BUF; k2 <<= 1) {
        #pragma unroll
        for (int j = k2 >> 1; j > 0; j >>= 1) {
            bool up    = (tid & k2) == 0;
            bool lower = (tid & j) == 0;
            bool keep_max = (up == lower);
            unsigned long long o;
            if (j >= 32) {
                s.cand[tid] = v;
                __syncthreads();
                o = s.cand[tid ^ j];
                __syncthreads();
            } else {
                o = __shfl_xor_sync(0xffffffffu, v, j);
            }
            v = keep_max ? (v >= o ? v : o) : (v >= o ? o : v);
        }
    }

    // ---- decode top-200 ----
    if (tid < TOP_K) {
        float sc  = __uint_as_float((unsigned)(v >> 32));
        int   idx = (int)(~(unsigned)v);
        bool valid = sc > CONF_TH;
        float x0 = 0.f, y0 = 0.f, x1 = 0.f, y1 = 0.f;
        if (valid) {
            const float4 l  = __ldg((const float4*)(loc + ((size_t)b * NUM_PRIORS + idx) * 4));
            const float4 pr = __ldg((const float4*)(prior + (size_t)idx * 4));
            float cx = pr.x + l.x * 0.1f * pr.z;
            float cy = pr.y + l.y * 0.1f * pr.w;
            float w  = pr.z * expf(l.z * 0.2f);
            float h  = pr.w * expf(l.w * 0.2f);
            x0 = cx - w * 0.5f; y0 = cy - h * 0.5f;
            x1 = cx + w * 0.5f; y1 = cy + h * 0.5f;
        }
        s.bx0[tid] = x0; s.by0[tid] = y0;
        s.bx1[tid] = x1; s.by1[tid] = y1;
        s.score[tid] = sc;
        s.area[tid]  = (x1 - x0) * (y1 - y0);
    }
    if (tid < 8) s.keepw[tid] = 0u;
    __syncthreads();

    // ---- build suppression bitmask; only words w >= i>>5 (fold reads same range) ----
    {
        const int warp = tid >> 5, lane = tid & 31;
        for (int i = warp; i < TOP_K; i += FINAL_NT / 32) {
            float ix0 = s.bx0[i], iy0 = s.by0[i];
            float ix1 = s.bx1[i], iy1 = s.by1[i];
            float ia  = s.area[i];
            const int iw = i >> 5;
            for (int w = iw; w < NWORDS; ++w) {
                int j = (w << 5) + lane;
                bool sup = false;
                if (j < TOP_K && j > i) {
                    float ww = fminf(ix1, s.bx1[j]) - fmaxf(ix0, s.bx0[j]);
                    float hh = fminf(iy1, s.by1[j]) - fmaxf(iy0, s.by0[j]);
                    ww = fmaxf(ww, 0.f); hh = fmaxf(hh, 0.f);
                    float inter = ww * hh;
                    float uni = ia + s.area[j] - inter;
                    sup = inter > NMS_TH * fmaxf(uni, 1e-12f);
                }
                unsigned bal = __ballot_sync(0xffffffffu, sup);
                if (lane == 0) s.sup[i][w] = bal;
            }
        }
        if (warp < NWORDS) {
            int j = (warp << 5) + lane;
            bool val = (j < TOP_K) && (s.score[j] > CONF_TH);
            unsigned bal = __ballot_sync(0xffffffffu, val);
            if (lane == 0) s.keepw[warp] = bal;
        }
    }
    __syncthreads();

    // ---- register-resident NMS fold (warp 0, lanes replicated/broadcast LDS) ----
    if (tid < 32) {
        unsigned k[NWORDS];
        #pragma unroll
        for (int w = 0; w < NWORDS; ++w) k[w] = s.keepw[w];
        fold_word<0>(k, s.sup, 32);
        fold_word<1>(k, s.sup, 32);
        fold_word<2>(k, s.sup, 32);
        fold_word<3>(k, s.sup, 32);
        fold_word<4>(k, s.sup, 32);
        fold_word<5>(k, s.sup, 32);
        fold_word<6>(k, s.sup, TOP_K - 6 * 32);   // 8 bits
        if (tid == 0) {
            #pragma unroll
            for (int w = 0; w < NWORDS; ++w) s.keepw[w] = k[w];
        }
    }
    __syncthreads();

    // ---- write output ----
    float* ob = out + (size_t)b * 2 * TOP_K * 5;
    for (int i = tid; i < 2 * TOP_K * 5; i += NT) ob[i] = 0.f;
    __syncthreads();

    if (tid < TOP_K) {
        int w = tid >> 5, bit = tid & 31;
        unsigned mw = s.keepw[w];
        if ((mw >> bit) & 1u) {
            int pos = 0;
            #pragma unroll
            for (int kk = 0; kk < NWORDS; ++kk)
                if (kk < w) pos += __popc(s.keepw[kk]);
            pos += __popc(mw & ((1u << bit) - 1u));
            float* r = ob + (size_t)TOP_K * 5 + (size_t)pos * 5;
            r[0] = s.score[tid];
            r[1] = s.bx0[tid];
            r[2] = s.by0[tid];
            r[3] = s.bx1[tid];
            r[4] = s.by1[tid];
        }
    }
}

extern "C" void kernel_launch(void* const* d_in, const int* in_sizes, int n_in,
                              void* d_out, int out_size)
{
    const float*  locp  = (const float*)d_in[0];
    const float2* conf2 = (const float2*)d_in[1];
    const float4* conf4 = (const float4*)d_in[1];
    const float*  prior = (const float*)d_in[2];
    float* out = (float*)d_out;

    dim3 gA(SLICES, BATCH);
    scan_kernel<<<gA, 256>>>(conf4);

    const int smem_bytes = (int)sizeof(Smem);
    cudaFuncSetAttribute(final_kernel, cudaFuncAttributeMaxDynamicSharedMemorySize, smem_bytes);
    final_kernel<<<BATCH, FINAL_NT, smem_bytes>>>(locp, conf2, prior, out);
}

// round 8
// speedup vs baseline: 1.7391x; 1.1403x over previous
#include <cuda_runtime.h>
#include <cuda_bf16.h>
#include <math.h>

// SSD detection post-processing, two-phase.
//   d_in[0]: loc_data   [64, 72192, 4] float32
//   d_in[1]: conf_data  [64*72192, 2]  float32
//   d_in[2]: prior_data [72192, 4]     float32
// Output: [64, 2, 200, 5] float32 (class 0 zeros; class 1 = NMS results)

#define NUM_PRIORS 72192
#define BATCH      64
#define TOP_K      200
#define CAND_BUF   512
#define HIST_BINS  4096
#define BIN_SHIFT  14
#define BIN_OFF    61440
#define CONF_TH    0.01f
#define NMS_TH     0.45f
#define SPEC_TH    0.9958f      // expected ~303 survivors/batch (uniform scores)
#define NWORDS     7            // ceil(200/32)
#define SUPW       9            // padded row width (bank-conflict-free lane loads)
#define SLICES     32
#define PRIORS_PER_SLICE (NUM_PRIORS / SLICES)   // 2256
#define FINAL_NT   512

// ---- global scratch (zero-init at load; final_kernel self-resets) ----
__device__ unsigned long long g_cand[BATCH][CAND_BUF];
__device__ int g_cnt[BATCH];

// ============================ kernel A: scan + gather (+ zero output) ============================
__global__ __launch_bounds__(256)
void scan_kernel(const float4* __restrict__ conf4, float* __restrict__ out)
{
    const int b     = blockIdx.y;
    const int slice = blockIdx.x;
    const int tid   = threadIdx.x;

    // slice-0 CTAs zero this batch's output in parallel with the scan
    if (slice == 0) {
        float* ob = out + (size_t)b * 2 * TOP_K * 5;
        #pragma unroll
        for (int i = tid; i < 2 * TOP_K * 5; i += 256) ob[i] = 0.f;
    }

    const int pair_base = (b * NUM_PRIORS + slice * PRIORS_PER_SLICE) >> 1;
    const int npairs    = PRIORS_PER_SLICE >> 1;          // 1128
    const int p_base    = slice * PRIORS_PER_SLICE;

    // MLP=2: two independent float4 loads in flight per iteration
    for (int i = tid; i < npairs; i += 512) {
        float4 v1 = conf4[pair_base + i];
        bool has2 = (i + 256) < npairs;
        float4 v2 = has2 ? conf4[pair_base + i + 256] : make_float4(0.f, 0.f, 0.f, 0.f);

        int p0 = p_base + 2 * i;
        if (v1.y >= SPEC_TH) {
            int q = atomicAdd(&g_cnt[b], 1);
            if (q < CAND_BUF)
                g_cand[b][q] = ((unsigned long long)__float_as_uint(v1.y) << 32)
                             | (unsigned)(~p0);
        }
        if (v1.w >= SPEC_TH) {
            int q = atomicAdd(&g_cnt[b], 1);
            if (q < CAND_BUF)
                g_cand[b][q] = ((unsigned long long)__float_as_uint(v1.w) << 32)
                             | (unsigned)(~(p0 + 1));
        }
        if (has2) {
            int p2 = p_base + 2 * (i + 256);
            if (v2.y >= SPEC_TH) {
                int q = atomicAdd(&g_cnt[b], 1);
                if (q < CAND_BUF)
                    g_cand[b][q] = ((unsigned long long)__float_as_uint(v2.y) << 32)
                                 | (unsigned)(~p2);
            }
            if (v2.w >= SPEC_TH) {
                int q = atomicAdd(&g_cnt[b], 1);
                if (q < CAND_BUF)
                    g_cand[b][q] = ((unsigned long long)__float_as_uint(v2.w) << 32)
                                 | (unsigned)(~(p2 + 1));
            }
        }
    }
}

// ============================ kernel B: sort + NMS + write ============================
struct Smem {
    unsigned long long cand[CAND_BUF];   // 4 KB
    int      hist[HIST_BINS];            // 16 KB (fallback only)
    float    bx0[TOP_K], by0[TOP_K], bx1[TOP_K], by1[TOP_K];
    float    score[TOP_K], area[TOP_K];
    unsigned sup[TOP_K][SUPW];           // padded: lane loads conflict-free
    unsigned keepw[8];
    int      counter;
    int      thrbin;
};

__device__ __forceinline__ int score_bin(unsigned ub) {
    int v = (int)(ub >> BIN_SHIFT) - BIN_OFF;
    return v < 0 ? 0 : (v > HIST_BINS - 1 ? HIST_BINS - 1 : v);
}

__global__ __launch_bounds__(FINAL_NT, 1)
void final_kernel(const float* __restrict__ loc,
                  const float2* __restrict__ conf2,
                  const float* __restrict__ prior,
                  float* __restrict__ out)
{
    extern __shared__ unsigned char smem_raw[];
    Smem& s = *reinterpret_cast<Smem*>(smem_raw);

    const int b   = blockIdx.x;
    const int tid = threadIdx.x;
    const int NT  = FINAL_NT;

    const int cnt = g_cnt[b];
    __syncthreads();
    if (tid == 0) g_cnt[b] = 0;        // self-reset for graph replay

    unsigned long long v;

    if (cnt >= TOP_K && cnt <= CAND_BUF) {
        v = (tid < cnt) ? g_cand[b][tid] : 0ull;
    } else {
        // ---- exact fallback: full histogram select (handles cnt<TOP_K and overflow) ----
        const float2* cb = conf2 + (size_t)b * NUM_PRIORS;
        for (int i = tid; i < HIST_BINS; i += NT) s.hist[i] = 0;
        if (tid == 0) { s.counter = 0; s.thrbin = 0; }
        __syncthreads();
        for (int p = tid; p < NUM_PRIORS; p += NT) {
            float sc = cb[p].y;
            if (sc > CONF_TH) atomicAdd(&s.hist[score_bin(__float_as_uint(sc))], 1);
        }
        __syncthreads();
        if (tid == 0) {
            int cum = 0, thr = 0;
            for (int vb = HIST_BINS - 1; vb >= 0; --vb) {
                cum += s.hist[vb];
                if (cum >= TOP_K) { thr = vb; break; }
            }
            s.thrbin = thr;
        }
        __syncthreads();
        const int thr = s.thrbin;
        s.cand[tid] = 0ull;
        __syncthreads();
        for (int p = tid; p < NUM_PRIORS; p += NT) {
            float sc = cb[p].y;
            unsigned ub = __float_as_uint(sc);
            if (sc > CONF_TH && score_bin(ub) >= thr) {
                int q = atomicAdd(&s.counter, 1);
                if (q < CAND_BUF)
                    s.cand[q] = ((unsigned long long)ub << 32) | (unsigned)(~p);
            }
        }
        __syncthreads();
        v = s.cand[tid];
    }

    // ---- hybrid bitonic sort, 512 keys descending ----
    #pragma unroll
    for (int k2 = 2; k2 <= CAND_BUF; k2 <<= 1) {
        #pragma unroll
        for (int j = k2 >> 1; j > 0; j >>= 1) {
            bool up    = (tid & k2) == 0;
            bool lower = (tid & j) == 0;
            bool keep_max = (up == lower);
            unsigned long long o;
            if (j >= 32) {
                s.cand[tid] = v;
                __syncthreads();
                o = s.cand[tid ^ j];
                __syncthreads();
            } else {
                o = __shfl_xor_sync(0xffffffffu, v, j);
            }
            v = keep_max ? (v >= o ? v : o) : (v >= o ? o : v);
        }
    }

    // ---- decode top-200 ----
    if (tid < TOP_K) {
        float sc  = __uint_as_float((unsigned)(v >> 32));
        int   idx = (int)(~(unsigned)v);
        bool valid = sc > CONF_TH;
        float x0 = 0.f, y0 = 0.f, x1 = 0.f, y1 = 0.f;
        if (valid) {
            const float4 l  = __ldg((const float4*)(loc + ((size_t)b * NUM_PRIORS + idx) * 4));
            const float4 pr = __ldg((const float4*)(prior + (size_t)idx * 4));
            float cx = pr.x + l.x * 0.1f * pr.z;
            float cy = pr.y + l.y * 0.1f * pr.w;
            float w  = pr.z * expf(l.z * 0.2f);
            float h  = pr.w * expf(l.w * 0.2f);
            x0 = cx - w * 0.5f; y0 = cy - h * 0.5f;
            x1 = cx + w * 0.5f; y1 = cy + h * 0.5f;
        }
        s.bx0[tid] = x0; s.by0[tid] = y0;
        s.bx1[tid] = x1; s.by1[tid] = y1;
        s.score[tid] = sc;
        s.area[tid]  = (x1 - x0) * (y1 - y0);
    }
    if (tid < 8) s.keepw[tid] = 0u;
    __syncthreads();

    // ---- build suppression bitmask; only words w >= i>>5 (fold reads same range) ----
    {
        const int warp = tid >> 5, lane = tid & 31;
        for (int i = warp; i < TOP_K; i += FINAL_NT / 32) {
            float ix0 = s.bx0[i], iy0 = s.by0[i];
            float ix1 = s.bx1[i], iy1 = s.by1[i];
            float ia  = s.area[i];
            const int iw = i >> 5;
            for (int w = iw; w < NWORDS; ++w) {
                int j = (w << 5) + lane;
                bool sup = false;
                if (j < TOP_K && j > i) {
                    float ww = fminf(ix1, s.bx1[j]) - fmaxf(ix0, s.bx0[j]);
                    float hh = fminf(iy1, s.by1[j]) - fmaxf(iy0, s.by0[j]);
                    ww = fmaxf(ww, 0.f); hh = fmaxf(hh, 0.f);
                    float inter = ww * hh;
                    float uni = ia + s.area[j] - inter;
                    sup = inter > NMS_TH * fmaxf(uni, 1e-12f);
                }
                unsigned bal = __ballot_sync(0xffffffffu, sup);
                if (lane == 0) s.sup[i][w] = bal;
            }
        }
        if (warp < NWORDS) {
            int j = (warp << 5) + lane;
            bool val = (j < TOP_K) && (s.score[j] > CONF_TH);
            unsigned bal = __ballot_sync(0xffffffffu, val);
            if (lane == 0) s.keepw[warp] = bal;
        }
    }
    __syncthreads();

    // ---- NMS fold: prefetched within-word chain (ALU) + lane-parallel cross-word ----
    if (tid < 32) {
        unsigned k[NWORDS];
        #pragma unroll
        for (int w = 0; w < NWORDS; ++w) k[w] = s.keepw[w];

        #pragma unroll
        for (int W = 0; W < NWORDS; ++W) {
            const int nbits = (TOP_K - W * 32) < 32 ? (TOP_K - W * 32) : 32;
            // prefetch all within-word masks for this word (broadcast LDS, pipelined)
            unsigned rowW[32];
            #pragma unroll
            for (int bb = 0; bb < 32; ++bb)
                rowW[bb] = (bb < nbits) ? s.sup[W * 32 + bb][W] : 0u;
            // serial within-word fold: pure ALU chain
            unsigned kW = k[W];
            #pragma unroll
            for (int bb = 0; bb < 32; ++bb)
                if ((kW >> bb) & 1u) kW &= ~rowW[bb];
            k[W] = kW;
            // cross-word suppression: order-independent, lane-parallel + warp-OR
            if (W < NWORDS - 1) {
                bool kept = (tid < nbits) && ((kW >> tid) & 1u);
                #pragma unroll
                for (int w2 = W + 1; w2 < NWORDS; ++w2) {
                    unsigned a = kept ? s.sup[W * 32 + tid][w2] : 0u;
                    #pragma unroll
                    for (int o = 16; o > 0; o >>= 1)
                        a |= __shfl_xor_sync(0xffffffffu, a, o);
                    k[w2] &= ~a;
                }
            }
        }
        if (tid == 0) {
            #pragma unroll
            for (int w = 0; w < NWORDS; ++w) s.keepw[w] = k[w];
        }
    }
    __syncthreads();

    // ---- scatter kept rows (output already zeroed by scan kernel) ----
    if (tid < TOP_K) {
        int w = tid >> 5, bit = tid & 31;
        unsigned mw = s.keepw[w];
        if ((mw >> bit) & 1u) {
            int pos = 0;
            #pragma unroll
            for (int kk = 0; kk < NWORDS; ++kk)
                if (kk < w) pos += __popc(s.keepw[kk]);
            pos += __popc(mw & ((1u << bit) - 1u));
            float* r = out + (size_t)b * 2 * TOP_K * 5 + (size_t)TOP_K * 5 + (size_t)pos * 5;
            r[0] = s.score[tid];
            r[1] = s.bx0[tid];
            r[2] = s.by0[tid];
            r[3] = s.bx1[tid];
            r[4] = s.by1[tid];
        }
    }
}

extern "C" void kernel_launch(void* const* d_in, const int* in_sizes, int n_in,
                              void* d_out, int out_size)
{
    const float*  locp  = (const float*)d_in[0];
    const float2* conf2 = (const float2*)d_in[1];
    const float4* conf4 = (const float4*)d_in[1];
    const float*  prior = (const float*)d_in[2];
    float* out = (float*)d_out;

    dim3 gA(SLICES, BATCH);
    scan_kernel<<<gA, 256>>>(conf4, out);

    const int smem_bytes = (int)sizeof(Smem);
    cudaFuncSetAttribute(final_kernel, cudaFuncAttributeMaxDynamicSharedMemorySize, smem_bytes);
    final_kernel<<<BATCH, FINAL_NT, smem_bytes>>>(locp, conf2, prior, out);
}

// round 9
// speedup vs baseline: 1.8086x; 1.0400x over previous
#include <cuda_runtime.h>
#include <cuda_bf16.h>
#include <math.h>

// SSD detection post-processing, two-phase.
//   d_in[0]: loc_data   [64, 72192, 4] float32
//   d_in[1]: conf_data  [64*72192, 2]  float32
//   d_in[2]: prior_data [72192, 4]     float32
// Output: [64, 2, 200, 5] float32 (class 0 zeros; class 1 = NMS results)

#define NUM_PRIORS 72192
#define BATCH      64
#define TOP_K      200
#define CAND_BUF   512
#define HIST_BINS  4096
#define BIN_SHIFT  14
#define BIN_OFF    61440
#define CONF_TH    0.01f
#define NMS_TH     0.45f
#define SPEC_TH    0.9958f      // expected ~303 survivors/batch (uniform scores)
#define NWORDS     7            // ceil(200/32)
#define SUPW       9            // padded row width
#define SLICES     32
#define PRIORS_PER_SLICE (NUM_PRIORS / SLICES)   // 2256
#define FINAL_NT   512

// ---- global scratch (zero-init at load; final_kernel self-resets) ----
__device__ unsigned long long g_cand[BATCH][CAND_BUF];
__device__ int g_cnt[BATCH];

// ============================ kernel A: scan + gather (+ zero output) ============================
__global__ __launch_bounds__(256)
void scan_kernel(const float4* __restrict__ conf4, float* __restrict__ out)
{
    const int b     = blockIdx.y;
    const int slice = blockIdx.x;
    const int tid   = threadIdx.x;
    const int lane  = tid & 31;
    const unsigned ltm = (1u << lane) - 1u;

    if (slice == 0) {
        float* ob = out + (size_t)b * 2 * TOP_K * 5;
        #pragma unroll
        for (int i = tid; i < 2 * TOP_K * 5; i += 256) ob[i] = 0.f;
    }

    const int pair_base = (b * NUM_PRIORS + slice * PRIORS_PER_SLICE) >> 1;
    const int npairs    = PRIORS_PER_SLICE >> 1;          // 1128 -> up to 5 per thread
    const int p_base    = slice * PRIORS_PER_SLICE;

    // preload all strided values (MLP=5)
    float sy[5], sw[5];
    #pragma unroll
    for (int k = 0; k < 5; ++k) {
        int i = tid + k * 256;
        float4 v = (i < npairs) ? conf4[pair_base + i] : make_float4(0.f, 0.f, 0.f, 0.f);
        sy[k] = v.y; sw[k] = v.w;
    }

    #pragma unroll
    for (int k = 0; k < 5; ++k) {
        int i  = tid + k * 256;
        bool py = sy[k] >= SPEC_TH;       // OOB lanes have 0 -> false
        bool pw = sw[k] >= SPEC_TH;
        unsigned my = __ballot_sync(0xffffffffu, py);
        unsigned mw = __ballot_sync(0xffffffffu, pw);
        int tot = __popc(my) + __popc(mw);
        if (tot) {
            int base = 0;
            if (lane == 0) base = atomicAdd(&g_cnt[b], tot);
            base = __shfl_sync(0xffffffffu, base, 0);
            int p0 = p_base + 2 * i;
            if (py) {
                int q = base + __popc(my & ltm);
                if (q < CAND_BUF)
                    g_cand[b][q] = ((unsigned long long)__float_as_uint(sy[k]) << 32)
                                 | (unsigned)(~p0);
            }
            if (pw) {
                int q = base + __popc(my) + __popc(mw & ltm);
                if (q < CAND_BUF)
                    g_cand[b][q] = ((unsigned long long)__float_as_uint(sw[k]) << 32)
                                 | (unsigned)(~(p0 + 1));
            }
        }
    }
}

// ============================ kernel B: sort + NMS + write ============================
struct Smem {
    unsigned long long cand[CAND_BUF];    // 4 KB
    unsigned long long cand2[CAND_BUF];   // 4 KB (sort double buffer)
    int      hist[HIST_BINS];             // 16 KB (fallback only)
    float    bx0[TOP_K], by0[TOP_K], bx1[TOP_K], by1[TOP_K];
    float    score[TOP_K], area[TOP_K];
    unsigned sup[TOP_K][SUPW];
    unsigned keepw[8];
    int      counter;
    int      thrbin;
};

__device__ __forceinline__ int score_bin(unsigned ub) {
    int v = (int)(ub >> BIN_SHIFT) - BIN_OFF;
    return v < 0 ? 0 : (v > HIST_BINS - 1 ? HIST_BINS - 1 : v);
}

__global__ __launch_bounds__(FINAL_NT, 1)
void final_kernel(const float* __restrict__ loc,
                  const float2* __restrict__ conf2,
                  const float* __restrict__ prior,
                  float* __restrict__ out)
{
    extern __shared__ unsigned char smem_raw[];
    Smem& s = *reinterpret_cast<Smem*>(smem_raw);

    const int b   = blockIdx.x;
    const int tid = threadIdx.x;
    const int NT  = FINAL_NT;

    const int cnt = g_cnt[b];
    __syncthreads();
    if (tid == 0) g_cnt[b] = 0;

    unsigned long long v;

    if (cnt >= TOP_K && cnt <= CAND_BUF) {
        v = (tid < cnt) ? g_cand[b][tid] : 0ull;
    } else {
        // ---- exact fallback: full histogram select ----
        const float2* cb = conf2 + (size_t)b * NUM_PRIORS;
        for (int i = tid; i < HIST_BINS; i += NT) s.hist[i] = 0;
        if (tid == 0) { s.counter = 0; s.thrbin = 0; }
        __syncthreads();
        for (int p = tid; p < NUM_PRIORS; p += NT) {
            float sc = cb[p].y;
            if (sc > CONF_TH) atomicAdd(&s.hist[score_bin(__float_as_uint(sc))], 1);
        }
        __syncthreads();
        if (tid == 0) {
            int cum = 0, thr = 0;
            for (int vb = HIST_BINS - 1; vb >= 0; --vb) {
                cum += s.hist[vb];
                if (cum >= TOP_K) { thr = vb; break; }
            }
            s.thrbin = thr;
        }
        __syncthreads();
        const int thr = s.thrbin;
        s.cand[tid] = 0ull;
        __syncthreads();
        for (int p = tid; p < NUM_PRIORS; p += NT) {
            float sc = cb[p].y;
            unsigned ub = __float_as_uint(sc);
            if (sc > CONF_TH && score_bin(ub) >= thr) {
                int q = atomicAdd(&s.counter, 1);
                if (q < CAND_BUF)
                    s.cand[q] = ((unsigned long long)ub << 32) | (unsigned)(~p);
            }
        }
        __syncthreads();
        v = s.cand[tid];
    }

    // ---- hybrid bitonic sort, 512 keys descending; double-buffered cross-warp ----
    {
        unsigned long long* bufA = s.cand;
        unsigned long long* bufB = s.cand2;
        #pragma unroll
        for (int k2 = 2; k2 <= CAND_BUF; k2 <<= 1) {
            #pragma unroll
            for (int j = k2 >> 1; j > 0; j >>= 1) {
                bool keep_max = ((tid & k2) == 0) == ((tid & j) == 0);
                unsigned long long o;
                if (j >= 32) {
                    bufA[tid] = v;
                    __syncthreads();
                    o = bufA[tid ^ j];
                    unsigned long long* t = bufA; bufA = bufB; bufB = t;
                } else {
                    o = __shfl_xor_sync(0xffffffffu, v, j);
                }
                v = keep_max ? (v >= o ? v : o) : (v >= o ? o : v);
            }
        }
    }
    __syncthreads();   // sort epilogue: last phase read complete before smem reuse below

    // ---- decode top-200 ----
    if (tid < TOP_K) {
        float sc  = __uint_as_float((unsigned)(v >> 32));
        int   idx = (int)(~(unsigned)v);
        bool valid = sc > CONF_TH;
        float x0 = 0.f, y0 = 0.f, x1 = 0.f, y1 = 0.f;
        if (valid) {
            const float4 l  = __ldg((const float4*)(loc + ((size_t)b * NUM_PRIORS + idx) * 4));
            const float4 pr = __ldg((const float4*)(prior + (size_t)idx * 4));
            float cx = pr.x + l.x * 0.1f * pr.z;
            float cy = pr.y + l.y * 0.1f * pr.w;
            float w  = pr.z * expf(l.z * 0.2f);
            float h  = pr.w * expf(l.w * 0.2f);
            x0 = cx - w * 0.5f; y0 = cy - h * 0.5f;
            x1 = cx + w * 0.5f; y1 = cy + h * 0.5f;
        }
        s.bx0[tid] = x0; s.by0[tid] = y0;
        s.bx1[tid] = x1; s.by1[tid] = y1;
        s.score[tid] = sc;
        s.area[tid]  = (x1 - x0) * (y1 - y0);
    }
    if (tid < 8) s.keepw[tid] = 0u;
    __syncthreads();

    // ---- build suppression bitmask; only words w >= i>>5 ----
    {
        const int warp = tid >> 5, lane = tid & 31;
        for (int i = warp; i < TOP_K; i += FINAL_NT / 32) {
            float ix0 = s.bx0[i], iy0 = s.by0[i];
            float ix1 = s.bx1[i], iy1 = s.by1[i];
            float ia  = s.area[i];
            const int iw = i >> 5;
            for (int w = iw; w < NWORDS; ++w) {
                int j = (w << 5) + lane;
                bool sup = false;
                if (j < TOP_K && j > i) {
                    float ww = fminf(ix1, s.bx1[j]) - fmaxf(ix0, s.bx0[j]);
                    float hh = fminf(iy1, s.by1[j]) - fmaxf(iy0, s.by0[j]);
                    ww = fmaxf(ww, 0.f); hh = fmaxf(hh, 0.f);
                    float inter = ww * hh;
                    float uni = ia + s.area[j] - inter;
                    sup = inter > NMS_TH * fmaxf(uni, 1e-12f);
                }
                unsigned bal = __ballot_sync(0xffffffffu, sup);
                if (lane == 0) s.sup[i][w] = bal;
            }
        }
        if (warp < NWORDS) {
            int j = (warp << 5) + lane;
            bool val = (j < TOP_K) && (s.score[j] > CONF_TH);
            unsigned bal = __ballot_sync(0xffffffffu, val);
            if (lane == 0) s.keepw[warp] = bal;
        }
    }
    __syncthreads();

    // ---- NMS fold: prefetched within-word ALU chain + REDUX cross-word ----
    if (tid < 32) {
        unsigned k[NWORDS];
        #pragma unroll
        for (int w = 0; w < NWORDS; ++w) k[w] = s.keepw[w];

        #pragma unroll
        for (int W = 0; W < NWORDS; ++W) {
            const int nbits = (TOP_K - W * 32) < 32 ? (TOP_K - W * 32) : 32;
            unsigned rowW[32];
            #pragma unroll
            for (int bb = 0; bb < 32; ++bb)
                rowW[bb] = (bb < nbits) ? s.sup[W * 32 + bb][W] : 0u;
            unsigned kW = k[W];
            #pragma unroll
            for (int bb = 0; bb < 32; ++bb)
                if ((kW >> bb) & 1u) kW &= ~rowW[bb];
            k[W] = kW;
            if (W < NWORDS - 1) {
                bool kept = (tid < nbits) && ((kW >> tid) & 1u);
                #pragma unroll
                for (int w2 = W + 1; w2 < NWORDS; ++w2) {
                    unsigned a = kept ? s.sup[W * 32 + tid][w2] : 0u;
                    a = __reduce_or_sync(0xffffffffu, a);
                    k[w2] &= ~a;
                }
            }
        }
        if (tid == 0) {
            #pragma unroll
            for (int w = 0; w < NWORDS; ++w) s.keepw[w] = k[w];
        }
    }
    __syncthreads();

    // ---- scatter kept rows (output zeroed by scan kernel) ----
    if (tid < TOP_K) {
        int w = tid >> 5, bit = tid & 31;
        unsigned mw = s.keepw[w];
        if ((mw >> bit) & 1u) {
            int pos = 0;
            #pragma unroll
            for (int kk = 0; kk < NWORDS; ++kk)
                if (kk < w) pos += __popc(s.keepw[kk]);
            pos += __popc(mw & ((1u << bit) - 1u));
            float* r = out + (size_t)b * 2 * TOP_K * 5 + (size_t)TOP_K * 5 + (size_t)pos * 5;
            r[0] = s.score[tid];
            r[1] = s.bx0[tid];
            r[2] = s.by0[tid];
            r[3] = s.bx1[tid];
            r[4] = s.by1[tid];
        }
    }
}

extern "C" void kernel_launch(void* const* d_in, const int* in_sizes, int n_in,
                              void* d_out, int out_size)
{
    const float*  locp  = (const float*)d_in[0];
    const float2* conf2 = (const float2*)d_in[1];
    const float4* conf4 = (const float4*)d_in[1];
    const float*  prior = (const float*)d_in[2];
    float* out = (float*)d_out;

    dim3 gA(SLICES, BATCH);
    scan_kernel<<<gA, 256>>>(conf4, out);

    const int smem_bytes = (int)sizeof(Smem);
    cudaFuncSetAttribute(final_kernel, cudaFuncAttributeMaxDynamicSharedMemorySize, smem_bytes);
    final_kernel<<<BATCH, FINAL_NT, smem_bytes>>>(locp, conf2, prior, out);
}